// round 1
// baseline (speedup 1.0000x reference)
#include <cuda_runtime.h>

// Problem dims (fixed by the reference)
constexpr int STATE = 2048;
constexpr int SEQL  = 4096;
constexpr int HID   = 1024;

// Scratch: device globals (no allocation allowed in kernel_launch)
__device__ float g_proj[(size_t)SEQL * HID];   // 16 MB: proj = id @ W^T + b
__device__ float g_comb[(size_t)STATE * HID];  //  8 MB: w1*user + w2*social

// ---------------------------------------------------------------------------
// combine: g_comb = w1*user + w2*social   (elementwise, float4)
// ---------------------------------------------------------------------------
__global__ __launch_bounds__(256)
void combine_kernel(const float* __restrict__ u,
                    const float* __restrict__ s,
                    const float* __restrict__ w1p,
                    const float* __restrict__ w2p) {
    const float w1 = *w1p, w2 = *w2p;
    const int i = blockIdx.x * blockDim.x + threadIdx.x;   // float4 index
    const float4 uv = reinterpret_cast<const float4*>(u)[i];
    const float4 sv = reinterpret_cast<const float4*>(s)[i];
    float4 o;
    o.x = fmaf(w1, uv.x, w2 * sv.x);
    o.y = fmaf(w1, uv.y, w2 * sv.y);
    o.z = fmaf(w1, uv.z, w2 * sv.z);
    o.w = fmaf(w1, uv.w, w2 * sv.w);
    reinterpret_cast<float4*>(g_comb)[i] = o;
}

// ---------------------------------------------------------------------------
// NT GEMM: C[m,n] = sum_k A[m,k] * B[n,k] (+ bias[n])
// A: [M,K] row-major, B: [N,K] row-major. BM=BN=128, BK=16, 256 thr, 8x8/thr.
// All of M,N divisible by 128 and K by 16 for this problem -> no bounds checks.
// ---------------------------------------------------------------------------
template <bool HAS_BIAS>
__global__ __launch_bounds__(256)
void gemm_nt_kernel(const float* __restrict__ A, const float* __restrict__ B,
                    const float* __restrict__ bias, float* __restrict__ C,
                    int M, int N, int K) {
    constexpr int BM = 128, BN = 128, BK = 16, TM = 8, TN = 8;
    __shared__ float As[BK][BM];
    __shared__ float Bs[BK][BN];

    const int tid = threadIdx.x;
    const int m0  = blockIdx.y * BM;
    const int n0  = blockIdx.x * BN;
    const int tx  = tid & 15;   // n sub-tile (0..15)
    const int ty  = tid >> 4;   // m sub-tile (0..15)

    float acc[TM][TN];
    #pragma unroll
    for (int i = 0; i < TM; i++)
        #pragma unroll
        for (int j = 0; j < TN; j++) acc[i][j] = 0.f;

    for (int k0 = 0; k0 < K; k0 += BK) {
        // A tile: 128 x 16 = 512 float4 loads (2 per thread), transposed store
        #pragma unroll
        for (int it = 0; it < 2; ++it) {
            const int idx = tid + it * 256;       // 0..511
            const int row = idx >> 2;             // 0..127
            const int kq  = (idx & 3) << 2;       // 0,4,8,12
            const float4 v = *reinterpret_cast<const float4*>(
                &A[(size_t)(m0 + row) * K + k0 + kq]);
            As[kq + 0][row] = v.x; As[kq + 1][row] = v.y;
            As[kq + 2][row] = v.z; As[kq + 3][row] = v.w;
        }
        // B tile: 128 x 16, same pattern
        #pragma unroll
        for (int it = 0; it < 2; ++it) {
            const int idx = tid + it * 256;
            const int row = idx >> 2;
            const int kq  = (idx & 3) << 2;
            const float4 v = *reinterpret_cast<const float4*>(
                &B[(size_t)(n0 + row) * K + k0 + kq]);
            Bs[kq + 0][row] = v.x; Bs[kq + 1][row] = v.y;
            Bs[kq + 2][row] = v.z; Bs[kq + 3][row] = v.w;
        }
        __syncthreads();

        #pragma unroll
        for (int k = 0; k < BK; k++) {
            float ra[TM], rb[TN];
            #pragma unroll
            for (int i = 0; i < TM; i++) ra[i] = As[k][ty * TM + i];
            #pragma unroll
            for (int j = 0; j < TN; j++) rb[j] = Bs[k][tx * TN + j];
            #pragma unroll
            for (int i = 0; i < TM; i++)
                #pragma unroll
                for (int j = 0; j < TN; j++)
                    acc[i][j] = fmaf(ra[i], rb[j], acc[i][j]);
        }
        __syncthreads();
    }

    // Epilogue: float4 stores, optional bias add
    #pragma unroll
    for (int i = 0; i < TM; i++) {
        const int m = m0 + ty * TM + i;
        #pragma unroll
        for (int j = 0; j < TN; j += 4) {
            const int n = n0 + tx * TN + j;
            float4 v;
            v.x = acc[i][j]; v.y = acc[i][j + 1];
            v.z = acc[i][j + 2]; v.w = acc[i][j + 3];
            if (HAS_BIAS) {
                v.x += bias[n];     v.y += bias[n + 1];
                v.z += bias[n + 2]; v.w += bias[n + 3];
            }
            *reinterpret_cast<float4*>(&C[(size_t)m * N + n]) = v;
        }
    }
}

// ---------------------------------------------------------------------------
// Row softmax in place: one block per row of 4096 floats (row fits in smem)
// ---------------------------------------------------------------------------
__global__ __launch_bounds__(256)
void softmax_kernel(float* __restrict__ data) {
    constexpr int N = SEQL;                 // 4096
    __shared__ float sh[N];
    __shared__ float red[256];
    const int tid = threadIdx.x;
    float* row = data + (size_t)blockIdx.x * N;

    // Load row into smem (float4), track local max
    float mx = -3.402823466e38f;
    #pragma unroll
    for (int it = 0; it < 4; ++it) {
        const int i = tid + it * 256;       // float4 index, 0..1023
        const float4 v = reinterpret_cast<const float4*>(row)[i];
        reinterpret_cast<float4*>(sh)[i] = v;
        mx = fmaxf(mx, fmaxf(fmaxf(v.x, v.y), fmaxf(v.z, v.w)));
    }
    red[tid] = mx;
    __syncthreads();
    for (int s = 128; s > 0; s >>= 1) {
        if (tid < s) red[tid] = fmaxf(red[tid], red[tid + s]);
        __syncthreads();
    }
    mx = red[0];
    __syncthreads();

    // exp and local sum
    float sum = 0.f;
    #pragma unroll
    for (int it = 0; it < 4; ++it) {
        const int i = tid + it * 256;
        float4 v = reinterpret_cast<float4*>(sh)[i];
        v.x = expf(v.x - mx); v.y = expf(v.y - mx);
        v.z = expf(v.z - mx); v.w = expf(v.w - mx);
        reinterpret_cast<float4*>(sh)[i] = v;
        sum += v.x + v.y + v.z + v.w;
    }
    red[tid] = sum;
    __syncthreads();
    for (int s = 128; s > 0; s >>= 1) {
        if (tid < s) red[tid] += red[tid + s];
        __syncthreads();
    }
    const float inv = 1.f / red[0];

    #pragma unroll
    for (int it = 0; it < 4; ++it) {
        const int i = tid + it * 256;
        float4 v = reinterpret_cast<float4*>(sh)[i];
        v.x *= inv; v.y *= inv; v.z *= inv; v.w *= inv;
        reinterpret_cast<float4*>(row)[i] = v;
    }
}

// ---------------------------------------------------------------------------
// kernel_launch — graph-capturable, allocation-free
// ---------------------------------------------------------------------------
extern "C" void kernel_launch(void* const* d_in, const int* in_sizes, int n_in,
                              void* d_out, int out_size) {
    const float* user = (const float*)d_in[0];   // [STATE, HID]
    const float* id   = (const float*)d_in[1];   // [SEQL,  HID]
    const float* soc  = (const float*)d_in[2];   // [STATE, HID]
    const float* W    = (const float*)d_in[3];   // [HID,   HID]
    const float* b    = (const float*)d_in[4];   // [HID]
    const float* w1   = (const float*)d_in[5];   // scalar
    const float* w2   = (const float*)d_in[6];   // scalar
    float* out = (float*)d_out;                  // [STATE, SEQL]

    void* projPtr = nullptr;
    void* combPtr = nullptr;
    cudaGetSymbolAddress(&projPtr, g_proj);
    cudaGetSymbolAddress(&combPtr, g_comb);
    float* proj = (float*)projPtr;
    float* comb = (float*)combPtr;

    // 1) combined = w1*user + w2*social
    combine_kernel<<<(STATE * HID / 4) / 256, 256>>>(user, soc, w1, w2);

    // 2) proj[SEQL, HID] = id @ W^T + b    (NT GEMM, bias)
    gemm_nt_kernel<true><<<dim3(HID / 128, SEQL / 128), 256>>>(
        id, W, b, proj, SEQL, HID, HID);

    // 3) energies[STATE, SEQL] = comb @ proj^T   (NT GEMM) -> d_out
    gemm_nt_kernel<false><<<dim3(SEQL / 128, STATE / 128), 256>>>(
        comb, proj, nullptr, out, STATE, SEQL, HID);

    // 4) softmax rows in place
    softmax_kernel<<<STATE, 256>>>(out);
}